// round 1
// baseline (speedup 1.0000x reference)
#include <cuda_runtime.h>

// ---------------------------------------------------------------------------
// MHA: B=4, S=2048, D=512, H=8, HD=64
//   Qp = q@Wq^T+bq  (remapped to [B,H,S,HD]),  same K,V
//   flash attention per (b,h,128-row q tile)
//   out = ctx@Wo^T + bo
// All fp32; inner loops use packed f32x2 FMA (Blackwell FFMA2).
// ---------------------------------------------------------------------------

#define DI __device__ __forceinline__
typedef unsigned long long u64;

DI u64 pk2(float lo, float hi) {
    u64 r; asm("mov.b64 %0, {%1,%2};" : "=l"(r) : "f"(lo), "f"(hi)); return r;
}
DI void up2(u64 v, float& lo, float& hi) {
    asm("mov.b64 {%0,%1}, %2;" : "=f"(lo), "=f"(hi) : "l"(v));
}
DI void ffma2(u64& d, u64 a, u64 b) {
    asm("fma.rn.f32x2 %0, %1, %2, %0;" : "+l"(d) : "l"(a), "l"(b));
}
DI u64 fmul2(u64 a, u64 b) {
    u64 r; asm("mul.rn.f32x2 %0, %1, %2;" : "=l"(r) : "l"(a), "l"(b)); return r;
}

// scratch (allocation-free: device globals)
__device__ float g_q[8192 * 512];
__device__ float g_k[8192 * 512];
__device__ float g_v[8192 * 512];
__device__ float g_ctx[8192 * 512];

// ---------------------------------------------------------------------------
// GEMM: C[M=8192, N=512] = A[M,512] @ W[512,512]^T + bias
// REMAP=1: write to [B,H,S,HD] layout; REMAP=0: plain row-major [M,N].
// 128x128 tile, BK=16, 256 threads, 8x8 micro-tile, f32x2 acc over row-pairs.
// ---------------------------------------------------------------------------
template <int REMAP>
__global__ void __launch_bounds__(256)
gemm_kernel(const float* __restrict__ A, const float* __restrict__ W,
            const float* __restrict__ bias, float* __restrict__ C)
{
    const int K = 512;
    __shared__ float As[16][132];
    __shared__ float Bs[16][132];

    const int tid = threadIdx.x;
    const int ty = tid >> 4, tx = tid & 15;
    const int m0 = blockIdx.y * 128, n0 = blockIdx.x * 128;
    const int row0 = ty * 8, col0 = tx * 8;

    u64 acc[4][8];
#pragma unroll
    for (int rp = 0; rp < 4; rp++)
#pragma unroll
        for (int j = 0; j < 8; j++) acc[rp][j] = 0ull;

    for (int k0 = 0; k0 < K; k0 += 16) {
#pragma unroll
        for (int l = 0; l < 2; l++) {
            int idx = tid + l * 256;      // 0..511
            int m = idx >> 2;             // 0..127
            int kq = (idx & 3) << 2;      // 0,4,8,12
            float4 va = *(const float4*)&A[(m0 + m) * K + k0 + kq];
            As[kq + 0][m] = va.x; As[kq + 1][m] = va.y;
            As[kq + 2][m] = va.z; As[kq + 3][m] = va.w;
            float4 vw = *(const float4*)&W[(n0 + m) * K + k0 + kq];
            Bs[kq + 0][m] = vw.x; Bs[kq + 1][m] = vw.y;
            Bs[kq + 2][m] = vw.z; Bs[kq + 3][m] = vw.w;
        }
        __syncthreads();

#pragma unroll 8
        for (int kk = 0; kk < 16; kk++) {
            const float* ar = &As[kk][row0];
            u64 a[4];
            a[0] = *(const u64*)(ar + 0);
            a[1] = *(const u64*)(ar + 2);
            a[2] = *(const u64*)(ar + 4);
            a[3] = *(const u64*)(ar + 6);
            float4 b0 = *(const float4*)&Bs[kk][col0];
            float4 b1 = *(const float4*)&Bs[kk][col0 + 4];
            u64 bb[8];
            bb[0] = pk2(b0.x, b0.x); bb[1] = pk2(b0.y, b0.y);
            bb[2] = pk2(b0.z, b0.z); bb[3] = pk2(b0.w, b0.w);
            bb[4] = pk2(b1.x, b1.x); bb[5] = pk2(b1.y, b1.y);
            bb[6] = pk2(b1.z, b1.z); bb[7] = pk2(b1.w, b1.w);
#pragma unroll
            for (int rp = 0; rp < 4; rp++)
#pragma unroll
                for (int j = 0; j < 8; j++) ffma2(acc[rp][j], a[rp], bb[j]);
        }
        __syncthreads();
    }

    // epilogue: bias + store (float4 per row-quad)
    float bv[8];
#pragma unroll
    for (int j = 0; j < 8; j++) bv[j] = bias[n0 + col0 + j];

#pragma unroll
    for (int rp = 0; rp < 4; rp++) {
        float v0[8], v1[8];
#pragma unroll
        for (int j = 0; j < 8; j++) {
            up2(acc[rp][j], v0[j], v1[j]);
            v0[j] += bv[j]; v1[j] += bv[j];
        }
        int m = m0 + row0 + rp * 2;
#pragma unroll
        for (int half = 0; half < 2; half++) {
            const float* vv = half ? v1 : v0;
            int mm = m + half;
#pragma unroll
            for (int jj = 0; jj < 2; jj++) {
                int n = n0 + col0 + jj * 4;
                float4 o = make_float4(vv[jj*4+0], vv[jj*4+1], vv[jj*4+2], vv[jj*4+3]);
                if (REMAP) {
                    int bb2 = mm >> 11, s = mm & 2047;
                    int hh = n >> 6, hd = n & 63;
                    *(float4*)&C[(((bb2 << 3) + hh) * 2048 + s) * 64 + hd] = o;
                } else {
                    *(float4*)&C[mm * 512 + n] = o;
                }
            }
        }
    }
}

// ---------------------------------------------------------------------------
// Flash attention: one block = (b, h, 128 q-rows). 32 k-tiles of 64.
// 256 threads; micro-tile 8 rows (ty*8) x 4 interleaved cols (tx + 16j).
// ---------------------------------------------------------------------------
DI float wred_max(float v) {
    v = fmaxf(v, __shfl_xor_sync(0xffffffffu, v, 1));
    v = fmaxf(v, __shfl_xor_sync(0xffffffffu, v, 2));
    v = fmaxf(v, __shfl_xor_sync(0xffffffffu, v, 4));
    v = fmaxf(v, __shfl_xor_sync(0xffffffffu, v, 8));
    return v;
}
DI float wred_sum(float v) {
    v += __shfl_xor_sync(0xffffffffu, v, 1);
    v += __shfl_xor_sync(0xffffffffu, v, 2);
    v += __shfl_xor_sync(0xffffffffu, v, 4);
    v += __shfl_xor_sync(0xffffffffu, v, 8);
    return v;
}

#define ATTN_SMEM ((64*132 + 64*68 + 64*68 + 64*132) * 4)

__global__ void __launch_bounds__(256, 1)
attn_kernel(const float* __restrict__ Qp, const float* __restrict__ Kp,
            const float* __restrict__ Vp, float* __restrict__ ctx)
{
    extern __shared__ float sm[];
    float* QsT = sm;                          // [64 d][132]  (128 rows + pad)
    float* KsT = sm + 64 * 132;               // [64 d][68]   (64 cols + pad)
    float* Vs  = sm + 64 * 132 + 64 * 68;     // [64 c][68]   (64 d + pad)
    float* PsT = sm + 64 * 132 + 2 * 64 * 68; // [64 c][132]  (128 rows + pad)

    const int tid = threadIdx.x;
    const int ty = tid >> 4, tx = tid & 15;
    const int q0 = blockIdx.x * 128;
    const int h = blockIdx.y, b = blockIdx.z;
    const int base = ((b << 3) + h) * (2048 * 64);
    const int row0 = ty * 8;

    // load Q tile [128][64], transposed to d-major, pre-scaled by 1/sqrt(64)
#pragma unroll
    for (int l = 0; l < 8; l++) {
        int idx = tid + l * 256;
        int r = idx >> 4, dq = (idx & 15) << 2;
        float4 v = *(const float4*)&Qp[base + (q0 + r) * 64 + dq];
        QsT[(dq + 0) * 132 + r] = v.x * 0.125f;
        QsT[(dq + 1) * 132 + r] = v.y * 0.125f;
        QsT[(dq + 2) * 132 + r] = v.z * 0.125f;
        QsT[(dq + 3) * 132 + r] = v.w * 0.125f;
    }

    u64 o2[4][4];
#pragma unroll
    for (int rp = 0; rp < 4; rp++)
#pragma unroll
        for (int j = 0; j < 4; j++) o2[rp][j] = 0ull;
    float rm[8], rl[8];
#pragma unroll
    for (int i = 0; i < 8; i++) { rm[i] = -1e30f; rl[i] = 0.f; }

    for (int t = 0; t < 32; t++) {
        __syncthreads();
        const int c0 = t * 64;
#pragma unroll
        for (int l = 0; l < 4; l++) {
            int idx = tid + l * 256;
            int c = idx >> 4, dq = (idx & 15) << 2;
            float4 kv = *(const float4*)&Kp[base + (c0 + c) * 64 + dq];
            KsT[(dq + 0) * 68 + c] = kv.x;
            KsT[(dq + 1) * 68 + c] = kv.y;
            KsT[(dq + 2) * 68 + c] = kv.z;
            KsT[(dq + 3) * 68 + c] = kv.w;
            float4 vv = *(const float4*)&Vp[base + (c0 + c) * 64 + dq];
            *(float4*)&Vs[c * 68 + dq] = vv;
        }
        __syncthreads();

        // S = Q @ K^T  (rows packed in pairs)
        u64 s2[4][4];
#pragma unroll
        for (int rp = 0; rp < 4; rp++)
#pragma unroll
            for (int j = 0; j < 4; j++) s2[rp][j] = 0ull;

#pragma unroll 8
        for (int d = 0; d < 64; d++) {
            const float* qr = &QsT[d * 132 + row0];
            u64 a[4];
            a[0] = *(const u64*)(qr + 0);
            a[1] = *(const u64*)(qr + 2);
            a[2] = *(const u64*)(qr + 4);
            a[3] = *(const u64*)(qr + 6);
            const float* kr = &KsT[d * 68 + tx];
            u64 bb[4];
            { float v = kr[0];  bb[0] = pk2(v, v); }
            { float v = kr[16]; bb[1] = pk2(v, v); }
            { float v = kr[32]; bb[2] = pk2(v, v); }
            { float v = kr[48]; bb[3] = pk2(v, v); }
#pragma unroll
            for (int rp = 0; rp < 4; rp++)
#pragma unroll
                for (int j = 0; j < 4; j++) ffma2(s2[rp][j], a[rp], bb[j]);
        }

        // unpack scores, online softmax
        float sc[8][4];
#pragma unroll
        for (int rp = 0; rp < 4; rp++)
#pragma unroll
            for (int j = 0; j < 4; j++) up2(s2[rp][j], sc[2*rp][j], sc[2*rp+1][j]);

        float corr[8];
#pragma unroll
        for (int i = 0; i < 8; i++) {
            float mt = fmaxf(fmaxf(sc[i][0], sc[i][1]), fmaxf(sc[i][2], sc[i][3]));
            mt = wred_max(mt);
            float mn = fmaxf(rm[i], mt);
            corr[i] = __expf(rm[i] - mn);
            rm[i] = mn;
            float ls = 0.f;
#pragma unroll
            for (int j = 0; j < 4; j++) {
                float p = __expf(sc[i][j] - mn);
                sc[i][j] = p; ls += p;
            }
            ls = wred_sum(ls);
            rl[i] = rl[i] * corr[i] + ls;
        }
#pragma unroll
        for (int rp = 0; rp < 4; rp++) {
            u64 c2 = pk2(corr[2*rp], corr[2*rp+1]);
#pragma unroll
            for (int j = 0; j < 4; j++) o2[rp][j] = fmul2(o2[rp][j], c2);
        }

        // store P^T: [c][r]; interleaved cols -> conflict-free STS.128
#pragma unroll
        for (int j = 0; j < 4; j++) {
            int c = tx + (j << 4);
            *(float4*)&PsT[c * 132 + row0] =
                make_float4(sc[0][j], sc[1][j], sc[2][j], sc[3][j]);
            *(float4*)&PsT[c * 132 + row0 + 4] =
                make_float4(sc[4][j], sc[5][j], sc[6][j], sc[7][j]);
        }
        __syncthreads();

        // O += P @ V
#pragma unroll 8
        for (int c = 0; c < 64; c++) {
            const float* pr = &PsT[c * 132 + row0];
            u64 a[4];
            a[0] = *(const u64*)(pr + 0);
            a[1] = *(const u64*)(pr + 2);
            a[2] = *(const u64*)(pr + 4);
            a[3] = *(const u64*)(pr + 6);
            const float* vr = &Vs[c * 68 + tx];
            u64 bb[4];
            { float v = vr[0];  bb[0] = pk2(v, v); }
            { float v = vr[16]; bb[1] = pk2(v, v); }
            { float v = vr[32]; bb[2] = pk2(v, v); }
            { float v = vr[48]; bb[3] = pk2(v, v); }
#pragma unroll
            for (int rp = 0; rp < 4; rp++)
#pragma unroll
                for (int j = 0; j < 4; j++) ffma2(o2[rp][j], a[rp], bb[j]);
        }
    }

    // normalize and write ctx in [B,S,D] layout
#pragma unroll
    for (int rp = 0; rp < 4; rp++) {
        u64 iv = pk2(1.f / rl[2*rp], 1.f / rl[2*rp+1]);
        int r0g = q0 + row0 + rp * 2;
#pragma unroll
        for (int j = 0; j < 4; j++) {
            u64 r = fmul2(o2[rp][j], iv);
            float lo, hi; up2(r, lo, hi);
            int c = tx + (j << 4);
            ctx[(b * 2048 + r0g    ) * 512 + h * 64 + c] = lo;
            ctx[(b * 2048 + r0g + 1) * 512 + h * 64 + c] = hi;
        }
    }
}

// ---------------------------------------------------------------------------
extern "C" void kernel_launch(void* const* d_in, const int* in_sizes, int n_in,
                              void* d_out, int out_size)
{
    const float* q  = (const float*)d_in[0];
    const float* k  = (const float*)d_in[1];
    const float* v  = (const float*)d_in[2];
    const float* Wq = (const float*)d_in[3];
    const float* bq = (const float*)d_in[4];
    const float* Wk = (const float*)d_in[5];
    const float* bk = (const float*)d_in[6];
    const float* Wv = (const float*)d_in[7];
    const float* bv = (const float*)d_in[8];
    const float* Wo = (const float*)d_in[9];
    const float* bo = (const float*)d_in[10];

    float *gq, *gk, *gv, *gc;
    cudaGetSymbolAddress((void**)&gq, g_q);
    cudaGetSymbolAddress((void**)&gk, g_k);
    cudaGetSymbolAddress((void**)&gv, g_v);
    cudaGetSymbolAddress((void**)&gc, g_ctx);

    cudaFuncSetAttribute(attn_kernel,
                         cudaFuncAttributeMaxDynamicSharedMemorySize, ATTN_SMEM);

    dim3 gg(4, 64);
    gemm_kernel<1><<<gg, 256>>>(q, Wq, bq, gq);
    gemm_kernel<1><<<gg, 256>>>(k, Wk, bk, gk);
    gemm_kernel<1><<<gg, 256>>>(v, Wv, bv, gv);

    attn_kernel<<<dim3(16, 8, 4), 256, ATTN_SMEM>>>(gq, gk, gv, gc);

    gemm_kernel<0><<<gg, 256>>>(gc, Wo, bo, (float*)d_out);
}

// round 2
// speedup vs baseline: 1.9763x; 1.9763x over previous
#include <cuda_runtime.h>
#include <cuda_bf16.h>

// ---------------------------------------------------------------------------
// MHA via bf16 split-precision (hi+lo) mma.sync tensor cores.
// B=4, S=2048, D=512, H=8, HD=64.
//   proj GEMMs: C = A @ W^T + b  (128x64 tiles, BK=32, 3-term split MMA)
//   flash attn: per (b,h,128 q-rows), 64-col K tiles, P kept in registers
//   out GEMM:   ctx @ Wo^T + bo
// Split: x = hi(bf16) + lo(bf16(x-hi)); keep hi*hi + hi*lo + lo*hi.
// ---------------------------------------------------------------------------

#define DI __device__ __forceinline__

DI unsigned sptr(const void* p) {
    return (unsigned)__cvta_generic_to_shared(p);
}

DI void ldsm4(unsigned* r, unsigned a) {
    asm volatile("ldmatrix.sync.aligned.m8n8.x4.shared.b16 {%0,%1,%2,%3}, [%4];"
                 : "=r"(r[0]), "=r"(r[1]), "=r"(r[2]), "=r"(r[3]) : "r"(a));
}
DI void ldsm4t(unsigned* r, unsigned a) {
    asm volatile("ldmatrix.sync.aligned.m8n8.x4.trans.shared.b16 {%0,%1,%2,%3}, [%4];"
                 : "=r"(r[0]), "=r"(r[1]), "=r"(r[2]), "=r"(r[3]) : "r"(a));
}
DI void mma16816(float* c, const unsigned* a, const unsigned* b) {
    asm volatile(
        "mma.sync.aligned.m16n8k16.row.col.f32.bf16.bf16.f32 "
        "{%0,%1,%2,%3},{%4,%5,%6,%7},{%8,%9},{%0,%1,%2,%3};"
        : "+f"(c[0]), "+f"(c[1]), "+f"(c[2]), "+f"(c[3])
        : "r"(a[0]), "r"(a[1]), "r"(a[2]), "r"(a[3]), "r"(b[0]), "r"(b[1]));
}
// pack two fp32 -> bf16x2 (lo in low half)
DI unsigned pkbf(float lo, float hi) {
    unsigned r;
    asm("cvt.rn.bf16x2.f32 %0, %1, %2;" : "=r"(r) : "f"(hi), "f"(lo));
    return r;
}
DI float bfr(float x) {  // round to bf16 and back
    return __bfloat162float(__float2bfloat16(x));
}
DI void split2(float a, float b, unsigned& hi, unsigned& lo) {
    float ah = bfr(a), bh = bfr(b);
    hi = pkbf(ah, bh);
    lo = pkbf(a - ah, b - bh);
}
DI void split_store(float x, __nv_bfloat16* hi, __nv_bfloat16* lo) {
    __nv_bfloat16 h = __float2bfloat16(x);
    *hi = h;
    *lo = __float2bfloat16(x - __bfloat162float(h));
}

// scratch (allocation-free: device globals)
__device__ float g_q[8192 * 512];
__device__ float g_k[8192 * 512];
__device__ float g_v[8192 * 512];
__device__ float g_ctx[8192 * 512];

// ---------------------------------------------------------------------------
// GEMM: C[8192, 512] = A[8192,512] @ W[512,512]^T + bias
// Block 128(M) x 64(N), BK=32. 8 warps, warp w owns rows [16w,16w+16), all 64 N.
// ---------------------------------------------------------------------------
template <int REMAP>
__global__ void __launch_bounds__(256)
gemm_kernel(const float* __restrict__ A, const float* __restrict__ W,
            const float* __restrict__ bias, float* __restrict__ C)
{
    // bf16 planes, +8 pad per row (stride 40 elems = 80B, ldmatrix conflict-free)
    __shared__ __align__(16) __nv_bfloat16 Ahi[128 * 40], Alo[128 * 40];
    __shared__ __align__(16) __nv_bfloat16 Whi[64 * 40],  Wlo[64 * 40];

    const int tid = threadIdx.x;
    const int w = tid >> 5, lane = tid & 31;
    const int m0 = blockIdx.y * 128, n0 = blockIdx.x * 64;

    const unsigned ahi_b = sptr(Ahi), alo_b = sptr(Alo);
    const unsigned whi_b = sptr(Whi), wlo_b = sptr(Wlo);

    float acc[8][4];
#pragma unroll
    for (int j = 0; j < 8; j++)
#pragma unroll
        for (int i = 0; i < 4; i++) acc[j][i] = 0.f;

    for (int k0 = 0; k0 < 512; k0 += 32) {
        // load + split A tile 128x32
#pragma unroll
        for (int l = 0; l < 4; l++) {
            int idx = tid + l * 256;
            int r = idx >> 3, k4 = (idx & 7) << 2;
            float4 va = *(const float4*)&A[(m0 + r) * 512 + k0 + k4];
            split_store(va.x, &Ahi[r * 40 + k4 + 0], &Alo[r * 40 + k4 + 0]);
            split_store(va.y, &Ahi[r * 40 + k4 + 1], &Alo[r * 40 + k4 + 1]);
            split_store(va.z, &Ahi[r * 40 + k4 + 2], &Alo[r * 40 + k4 + 2]);
            split_store(va.w, &Ahi[r * 40 + k4 + 3], &Alo[r * 40 + k4 + 3]);
        }
        // load + split W tile 64x32
#pragma unroll
        for (int l = 0; l < 2; l++) {
            int idx = tid + l * 256;
            int r = idx >> 3, k4 = (idx & 7) << 2;
            float4 vw = *(const float4*)&W[(n0 + r) * 512 + k0 + k4];
            split_store(vw.x, &Whi[r * 40 + k4 + 0], &Wlo[r * 40 + k4 + 0]);
            split_store(vw.y, &Whi[r * 40 + k4 + 1], &Wlo[r * 40 + k4 + 1]);
            split_store(vw.z, &Whi[r * 40 + k4 + 2], &Wlo[r * 40 + k4 + 2]);
            split_store(vw.w, &Whi[r * 40 + k4 + 3], &Wlo[r * 40 + k4 + 3]);
        }
        __syncthreads();

#pragma unroll
        for (int ks = 0; ks < 2; ks++) {
            unsigned aoff = ((w * 16 + (lane & 15)) * 40 + ks * 16 + ((lane >> 4) << 3)) * 2;
            unsigned ah[4], al[4];
            ldsm4(ah, ahi_b + aoff);
            ldsm4(al, alo_b + aoff);
#pragma unroll
            for (int np = 0; np < 4; np++) {
                unsigned boff = ((np * 16 + (lane & 7) + ((lane >> 4) << 3)) * 40
                                 + ks * 16 + ((lane >> 3) & 1) * 8) * 2;
                unsigned bh[4], bl[4];
                ldsm4(bh, whi_b + boff);
                ldsm4(bl, wlo_b + boff);
                mma16816(acc[np * 2],     ah, bh);
                mma16816(acc[np * 2],     ah, bl);
                mma16816(acc[np * 2],     al, bh);
                mma16816(acc[np * 2 + 1], ah, bh + 2);
                mma16816(acc[np * 2 + 1], ah, bl + 2);
                mma16816(acc[np * 2 + 1], al, bh + 2);
            }
        }
        __syncthreads();
    }

    // epilogue: bias + store
#pragma unroll
    for (int j = 0; j < 8; j++) {
        int n = n0 + j * 8 + (lane & 3) * 2;
        float b0 = bias[n], b1 = bias[n + 1];
#pragma unroll
        for (int rr = 0; rr < 2; rr++) {
            int m = m0 + w * 16 + (lane >> 2) + rr * 8;
            float2 val = make_float2(acc[j][rr * 2] + b0, acc[j][rr * 2 + 1] + b1);
            if (REMAP) {
                int bb = m >> 11, s = m & 2047;
                int hh = n >> 6, hd = n & 63;
                *(float2*)&C[(((bb << 3) + hh) * 2048 + s) * 64 + hd] = val;
            } else {
                *(float2*)&C[m * 512 + n] = val;
            }
        }
    }
}

// ---------------------------------------------------------------------------
// Flash attention: block = (b, h, 128 q-rows). 32 K-tiles of 64 cols.
// 8 warps x 16 rows. P stays in registers (S C-frag == PV A-frag layout).
// ---------------------------------------------------------------------------
__global__ void __launch_bounds__(256)
attn_kernel(const float* __restrict__ Qp, const float* __restrict__ Kp,
            const float* __restrict__ Vp, float* __restrict__ ctx)
{
    // 18432 bf16 = 36864B. Aliased: Q staging (2 planes of 128x72) OR K/V
    // tiles (4 planes of 64x72).
    __shared__ __align__(16) __nv_bfloat16 smb[18432];
    __nv_bfloat16* Qhi = smb;
    __nv_bfloat16* Qlo = smb + 9216;
    __nv_bfloat16* Khi = smb;
    __nv_bfloat16* Klo = smb + 4608;
    __nv_bfloat16* Vhi = smb + 9216;
    __nv_bfloat16* Vlo = smb + 13824;

    const int tid = threadIdx.x;
    const int w = tid >> 5, lane = tid & 31;
    const int q0 = blockIdx.x * 128;
    const int h = blockIdx.y, b = blockIdx.z;
    const long base = (long)((b << 3) + h) * (2048 * 64);

    // ---- load Q tile 128x64, scale by 1/8, split into bf16 planes ----
#pragma unroll
    for (int l = 0; l < 8; l++) {
        int idx = tid + l * 256;
        int r = idx >> 4, d4 = (idx & 15) << 2;
        float4 v = *(const float4*)&Qp[base + (q0 + r) * 64 + d4];
        split_store(v.x * 0.125f, &Qhi[r * 72 + d4 + 0], &Qlo[r * 72 + d4 + 0]);
        split_store(v.y * 0.125f, &Qhi[r * 72 + d4 + 1], &Qlo[r * 72 + d4 + 1]);
        split_store(v.z * 0.125f, &Qhi[r * 72 + d4 + 2], &Qlo[r * 72 + d4 + 2]);
        split_store(v.w * 0.125f, &Qhi[r * 72 + d4 + 3], &Qlo[r * 72 + d4 + 3]);
    }
    __syncthreads();

    // ---- Q fragments to registers (persist whole kernel) ----
    unsigned qh[4][4], ql[4][4];
    {
        unsigned qrow = (w * 16 + (lane & 15)) * 72;
        unsigned qhi_b = sptr(Qhi), qlo_b = sptr(Qlo);
#pragma unroll
        for (int ks = 0; ks < 4; ks++) {
            unsigned off = (qrow + ks * 16 + ((lane >> 4) << 3)) * 2;
            ldsm4(qh[ks], qhi_b + off);
            ldsm4(ql[ks], qlo_b + off);
        }
    }
    __syncthreads();

    const unsigned khi_b = sptr(Khi), klo_b = sptr(Klo);
    const unsigned vhi_b = sptr(Vhi), vlo_b = sptr(Vlo);

    float o[8][4];
#pragma unroll
    for (int j = 0; j < 8; j++)
#pragma unroll
        for (int i = 0; i < 4; i++) o[j][i] = 0.f;
    float rm[2] = {-1e30f, -1e30f}, rl[2] = {0.f, 0.f};

    for (int t = 0; t < 32; t++) {
        const int c0 = t * 64;
        // ---- fill K/V tiles (64x64 each), split ----
#pragma unroll
        for (int l = 0; l < 4; l++) {
            int idx = tid + l * 256;
            int c = idx >> 4, d4 = (idx & 15) << 2;
            float4 kv = *(const float4*)&Kp[base + (c0 + c) * 64 + d4];
            split_store(kv.x, &Khi[c * 72 + d4 + 0], &Klo[c * 72 + d4 + 0]);
            split_store(kv.y, &Khi[c * 72 + d4 + 1], &Klo[c * 72 + d4 + 1]);
            split_store(kv.z, &Khi[c * 72 + d4 + 2], &Klo[c * 72 + d4 + 2]);
            split_store(kv.w, &Khi[c * 72 + d4 + 3], &Klo[c * 72 + d4 + 3]);
            float4 vv = *(const float4*)&Vp[base + (c0 + c) * 64 + d4];
            split_store(vv.x, &Vhi[c * 72 + d4 + 0], &Vlo[c * 72 + d4 + 0]);
            split_store(vv.y, &Vhi[c * 72 + d4 + 1], &Vlo[c * 72 + d4 + 1]);
            split_store(vv.z, &Vhi[c * 72 + d4 + 2], &Vlo[c * 72 + d4 + 2]);
            split_store(vv.w, &Vhi[c * 72 + d4 + 3], &Vlo[c * 72 + d4 + 3]);
        }
        __syncthreads();

        // ---- S = Q @ K^T ----
        float s[8][4];
#pragma unroll
        for (int j = 0; j < 8; j++)
#pragma unroll
            for (int i = 0; i < 4; i++) s[j][i] = 0.f;

#pragma unroll
        for (int ks = 0; ks < 4; ks++) {
#pragma unroll
            for (int np = 0; np < 4; np++) {
                unsigned boff = ((np * 16 + (lane & 7) + ((lane >> 4) << 3)) * 72
                                 + ks * 16 + ((lane >> 3) & 1) * 8) * 2;
                unsigned bh[4], bl[4];
                ldsm4(bh, khi_b + boff);
                ldsm4(bl, klo_b + boff);
                mma16816(s[np * 2],     qh[ks], bh);
                mma16816(s[np * 2],     qh[ks], bl);
                mma16816(s[np * 2],     ql[ks], bh);
                mma16816(s[np * 2 + 1], qh[ks], bh + 2);
                mma16816(s[np * 2 + 1], qh[ks], bl + 2);
                mma16816(s[np * 2 + 1], ql[ks], bh + 2);
            }
        }

        // ---- online softmax (rows: lane/4 and lane/4+8) ----
#pragma unroll
        for (int rr = 0; rr < 2; rr++) {
            float mt = -1e30f;
#pragma unroll
            for (int j = 0; j < 8; j++)
                mt = fmaxf(mt, fmaxf(s[j][rr * 2], s[j][rr * 2 + 1]));
            mt = fmaxf(mt, __shfl_xor_sync(0xffffffffu, mt, 1));
            mt = fmaxf(mt, __shfl_xor_sync(0xffffffffu, mt, 2));
            float mn = fmaxf(rm[rr], mt);
            float corr = __expf(rm[rr] - mn);
            rm[rr] = mn;
            float ls = 0.f;
#pragma unroll
            for (int j = 0; j < 8; j++) {
                float p0 = __expf(s[j][rr * 2] - mn);
                float p1 = __expf(s[j][rr * 2 + 1] - mn);
                s[j][rr * 2] = p0; s[j][rr * 2 + 1] = p1;
                ls += p0 + p1;
            }
            ls += __shfl_xor_sync(0xffffffffu, ls, 1);
            ls += __shfl_xor_sync(0xffffffffu, ls, 2);
            rl[rr] = rl[rr] * corr + ls;
#pragma unroll
            for (int j = 0; j < 8; j++) {
                o[j][rr * 2] *= corr; o[j][rr * 2 + 1] *= corr;
            }
        }

        // ---- P fragments (S C-frag layout == PV A-frag layout) ----
        unsigned ph[4][4], pl[4][4];
#pragma unroll
        for (int kc = 0; kc < 4; kc++) {
            split2(s[2 * kc][0],     s[2 * kc][1],     ph[kc][0], pl[kc][0]);
            split2(s[2 * kc][2],     s[2 * kc][3],     ph[kc][1], pl[kc][1]);
            split2(s[2 * kc + 1][0], s[2 * kc + 1][1], ph[kc][2], pl[kc][2]);
            split2(s[2 * kc + 1][2], s[2 * kc + 1][3], ph[kc][3], pl[kc][3]);
        }

        // ---- O += P @ V ----
#pragma unroll
        for (int ks = 0; ks < 4; ks++) {
            unsigned vrow = ks * 16 + (lane & 7) + ((lane >> 3) & 1) * 8;
#pragma unroll
            for (int dp = 0; dp < 4; dp++) {
                unsigned off = (vrow * 72 + dp * 16 + ((lane >> 4) << 3)) * 2;
                unsigned bh[4], bl[4];
                ldsm4t(bh, vhi_b + off);
                ldsm4t(bl, vlo_b + off);
                mma16816(o[dp * 2],     ph[ks], bh);
                mma16816(o[dp * 2],     ph[ks], bl);
                mma16816(o[dp * 2],     pl[ks], bh);
                mma16816(o[dp * 2 + 1], ph[ks], bh + 2);
                mma16816(o[dp * 2 + 1], ph[ks], bl + 2);
                mma16816(o[dp * 2 + 1], pl[ks], bh + 2);
            }
        }
        __syncthreads();
    }

    // ---- normalize, write ctx [B,S,D] ----
#pragma unroll
    for (int rr = 0; rr < 2; rr++) {
        float inv = 1.f / rl[rr];
        int rg = q0 + w * 16 + (lane >> 2) + rr * 8;
#pragma unroll
        for (int j = 0; j < 8; j++) {
            int col = h * 64 + j * 8 + (lane & 3) * 2;
            float2 val = make_float2(o[j][rr * 2] * inv, o[j][rr * 2 + 1] * inv);
            *(float2*)&ctx[(b * 2048 + rg) * 512 + col] = val;
        }
    }
}

// ---------------------------------------------------------------------------
extern "C" void kernel_launch(void* const* d_in, const int* in_sizes, int n_in,
                              void* d_out, int out_size)
{
    const float* q  = (const float*)d_in[0];
    const float* k  = (const float*)d_in[1];
    const float* v  = (const float*)d_in[2];
    const float* Wq = (const float*)d_in[3];
    const float* bq = (const float*)d_in[4];
    const float* Wk = (const float*)d_in[5];
    const float* bk = (const float*)d_in[6];
    const float* Wv = (const float*)d_in[7];
    const float* bv = (const float*)d_in[8];
    const float* Wo = (const float*)d_in[9];
    const float* bo = (const float*)d_in[10];

    float *gq, *gk, *gv, *gc;
    cudaGetSymbolAddress((void**)&gq, g_q);
    cudaGetSymbolAddress((void**)&gk, g_k);
    cudaGetSymbolAddress((void**)&gv, g_v);
    cudaGetSymbolAddress((void**)&gc, g_ctx);

    dim3 gg(8, 64);
    gemm_kernel<1><<<gg, 256>>>(q, Wq, bq, gq);
    gemm_kernel<1><<<gg, 256>>>(k, Wk, bk, gk);
    gemm_kernel<1><<<gg, 256>>>(v, Wv, bv, gv);

    attn_kernel<<<dim3(16, 8, 4), 256>>>(gq, gk, gv, gc);

    gemm_kernel<0><<<gg, 256>>>(gc, Wo, bo, (float*)d_out);
}

// round 3
// speedup vs baseline: 2.5410x; 1.2857x over previous
#include <cuda_runtime.h>
#include <cuda_bf16.h>

// ---------------------------------------------------------------------------
// MHA, bf16 split-precision (hi+lo) tensor cores, cp.async pipelines.
// B=4, S=2048, D=512, H=8, HD=64.
//  0) convert: q,k,v,W* fp32 -> bf16 hi/lo planes
//  1) proj GEMMs (bf16-plane in, split-plane out, [B,H,S,HD] remap, Q scaled)
//  2) flash attn (pure bf16 tile copies via cp.async, P in registers)
//  3) out GEMM (split-plane in, fp32 out + bias)
// ---------------------------------------------------------------------------

#define DI __device__ __forceinline__

DI unsigned sptr(const void* p) { return (unsigned)__cvta_generic_to_shared(p); }

DI void cpasync16(unsigned dst, const void* src) {
    asm volatile("cp.async.cg.shared.global [%0], [%1], 16;" :: "r"(dst), "l"(src));
}
DI void cpcommit() { asm volatile("cp.async.commit_group;"); }
template <int N> DI void cpwait() { asm volatile("cp.async.wait_group %0;" :: "n"(N)); }

DI void ldsm4(unsigned* r, unsigned a) {
    asm volatile("ldmatrix.sync.aligned.m8n8.x4.shared.b16 {%0,%1,%2,%3}, [%4];"
                 : "=r"(r[0]), "=r"(r[1]), "=r"(r[2]), "=r"(r[3]) : "r"(a));
}
DI void ldsm4t(unsigned* r, unsigned a) {
    asm volatile("ldmatrix.sync.aligned.m8n8.x4.trans.shared.b16 {%0,%1,%2,%3}, [%4];"
                 : "=r"(r[0]), "=r"(r[1]), "=r"(r[2]), "=r"(r[3]) : "r"(a));
}
DI void mma16816(float* c, const unsigned* a, const unsigned* b) {
    asm volatile(
        "mma.sync.aligned.m16n8k16.row.col.f32.bf16.bf16.f32 "
        "{%0,%1,%2,%3},{%4,%5,%6,%7},{%8,%9},{%0,%1,%2,%3};"
        : "+f"(c[0]), "+f"(c[1]), "+f"(c[2]), "+f"(c[3])
        : "r"(a[0]), "r"(a[1]), "r"(a[2]), "r"(a[3]), "r"(b[0]), "r"(b[1]));
}
// pack two fp32 -> bf16x2 (first arg = element 0 / low half)
DI unsigned pkbf(float e0, float e1) {
    unsigned r;
    asm("cvt.rn.bf16x2.f32 %0, %1, %2;" : "=r"(r) : "f"(e1), "f"(e0));
    return r;
}
DI float bfr(float x) { return __bfloat162float(__float2bfloat16(x)); }
DI void split2(float a, float b, unsigned& hi, unsigned& lo) {
    float ah = bfr(a), bh = bfr(b);
    hi = pkbf(ah, bh);
    lo = pkbf(a - ah, b - bh);
}

// ---------------- scratch (allocation-free: device globals) ----------------
#define MD (8192 * 512)
#define WD (512 * 512)
__device__ __nv_bfloat16 g_qh[MD], g_ql[MD], g_kh[MD], g_kl[MD], g_vh[MD], g_vl[MD];
__device__ __nv_bfloat16 g_wqh[WD], g_wql[WD], g_wkh[WD], g_wkl[WD];
__device__ __nv_bfloat16 g_wvh[WD], g_wvl[WD], g_woh[WD], g_wol[WD];
__device__ __nv_bfloat16 g_Qh[MD], g_Ql[MD], g_Kh[MD], g_Kl[MD], g_Vh[MD], g_Vl[MD];
__device__ __nv_bfloat16 g_ch[MD], g_cl[MD];

// ---------------------------------------------------------------------------
// Convert: fp32 -> (hi, lo) bf16 planes. float4-granular grid-stride.
// ---------------------------------------------------------------------------
__global__ void convert_kernel(const float* __restrict__ src,
                               __nv_bfloat16* __restrict__ hi,
                               __nv_bfloat16* __restrict__ lo, int n4)
{
    int i = blockIdx.x * blockDim.x + threadIdx.x;
    int stride = gridDim.x * blockDim.x;
    for (; i < n4; i += stride) {
        float4 v = ((const float4*)src)[i];
        float hx = bfr(v.x), hy = bfr(v.y), hz = bfr(v.z), hw = bfr(v.w);
        uint2 h, l;
        h.x = pkbf(hx, hy);          h.y = pkbf(hz, hw);
        l.x = pkbf(v.x - hx, v.y - hy); l.y = pkbf(v.z - hz, v.w - hw);
        ((uint2*)hi)[i] = h;
        ((uint2*)lo)[i] = l;
    }
}

// ---------------------------------------------------------------------------
// GEMM: C[8192,512] = A @ W^T (+bias) (*scale). bf16 hi/lo planes in.
// Tile 128Mx128N, BK=32, 256 thr, warps 2(M)x4(N): warp = 64Mx32N.
// 2-stage cp.async. OUT_SPLIT=1: split planes + [B,H,S,HD] remap.
// smem/stage: Ahi,Alo,Whi,Wlo each 128x40 bf16 (pad 8) = 10240B -> 40960B.
// ---------------------------------------------------------------------------
#define GSTG 40960
template <int OUT_SPLIT>
__global__ void __launch_bounds__(256, 2)
gemm_bf16(const __nv_bfloat16* __restrict__ Ahi, const __nv_bfloat16* __restrict__ Alo,
          const __nv_bfloat16* __restrict__ Whi, const __nv_bfloat16* __restrict__ Wlo,
          const float* __restrict__ bias, float scale,
          float* __restrict__ Cf,
          __nv_bfloat16* __restrict__ Chi, __nv_bfloat16* __restrict__ Clo)
{
    extern __shared__ __align__(16) unsigned char dsm[];
    const unsigned smb = sptr(dsm);
    const int tid = threadIdx.x, w = tid >> 5, lane = tid & 31;
    const int wm = w >> 2, wn = w & 3;
    const int m0 = blockIdx.y * 128, n0 = blockIdx.x * 128;

    float acc[4][4][4];
#pragma unroll
    for (int a = 0; a < 4; a++)
#pragma unroll
        for (int b = 0; b < 4; b++)
#pragma unroll
            for (int c = 0; c < 4; c++) acc[a][b][c] = 0.f;

    // chunk map: idx = tid + c*256 in [0,2048): p=idx>>9 plane, r=(idx>>2)&127, q=idx&3
    const int c_p = tid >> 9;  // always 0 for 256 threads; recompute per c below

#pragma unroll 1
    for (int step = -1; step < 16; step++) {
        int lt = step + 1;
        if (lt < 16) {  // issue loads for tile lt
            unsigned sdst = smb + (lt & 1) * GSTG;
            int k0 = lt * 32;
#pragma unroll
            for (int c = 0; c < 8; c++) {
                int idx = tid + c * 256;
                int p = idx >> 9, r = (idx >> 2) & 127, q = idx & 3;
                const __nv_bfloat16* sp = (p == 0) ? Ahi : (p == 1) ? Alo
                                         : (p == 2) ? Whi : Wlo;
                int grow = ((p < 2) ? m0 : n0) + r;
                cpasync16(sdst + p * 10240 + r * 80 + q * 16,
                          sp + grow * 512 + k0 + q * 8);
            }
            cpcommit();
        }
        if (step < 0) continue;
        if (step < 15) cpwait<1>(); else cpwait<0>();
        __syncthreads();

        unsigned sa = smb + (step & 1) * GSTG;
#pragma unroll
        for (int ks = 0; ks < 2; ks++) {
            unsigned bh[2][4], bl[2][4];
#pragma unroll
            for (int np = 0; np < 2; np++) {
                unsigned boff = ((wn * 32 + np * 16 + (lane & 7) + ((lane >> 4) << 3)) * 40
                                 + ks * 16 + ((lane >> 3) & 1) * 8) * 2;
                ldsm4(bh[np], sa + 20480 + boff);
                ldsm4(bl[np], sa + 30720 + boff);
            }
#pragma unroll
            for (int mi = 0; mi < 4; mi++) {
                unsigned aoff = ((wm * 64 + mi * 16 + (lane & 15)) * 40
                                 + ks * 16 + ((lane >> 4) << 3)) * 2;
                unsigned ah[4], al[4];
                ldsm4(ah, sa + aoff);
                ldsm4(al, sa + 10240 + aoff);
#pragma unroll
                for (int np = 0; np < 2; np++) {
                    mma16816(acc[mi][np * 2],     ah, bh[np]);
                    mma16816(acc[mi][np * 2],     ah, bl[np]);
                    mma16816(acc[mi][np * 2],     al, bh[np]);
                    mma16816(acc[mi][np * 2 + 1], ah, bh[np] + 2);
                    mma16816(acc[mi][np * 2 + 1], ah, bl[np] + 2);
                    mma16816(acc[mi][np * 2 + 1], al, bh[np] + 2);
                }
            }
        }
        __syncthreads();
    }
    (void)c_p;

    // epilogue
#pragma unroll
    for (int mi = 0; mi < 4; mi++) {
#pragma unroll
        for (int j = 0; j < 4; j++) {
            int n = n0 + wn * 32 + (j >> 1) * 16 + (j & 1) * 8 + (lane & 3) * 2;
            float b0 = bias[n], b1 = bias[n + 1];
#pragma unroll
            for (int rr = 0; rr < 2; rr++) {
                int m = m0 + wm * 64 + mi * 16 + (lane >> 2) + rr * 8;
                float v0 = (acc[mi][j][rr * 2]     + b0) * scale;
                float v1 = (acc[mi][j][rr * 2 + 1] + b1) * scale;
                if (OUT_SPLIT) {
                    int bb = m >> 11, s = m & 2047, hh = n >> 6, hd = n & 63;
                    int o = (((bb << 3) + hh) * 2048 + s) * 64 + hd;
                    unsigned hv, lv; split2(v0, v1, hv, lv);
                    *(unsigned*)&Chi[o] = hv;
                    *(unsigned*)&Clo[o] = lv;
                } else {
                    *(float2*)&Cf[m * 512 + n] = make_float2(v0, v1);
                }
            }
        }
    }
}

// ---------------------------------------------------------------------------
// Flash attention. Block = (b,h,128 q rows). 32 K-tiles of 64.
// Inputs are pre-split bf16 planes [B,H,S,HD]. cp.async 2-stage K/V pipeline.
// smem/stage: Khi,Klo,Vhi,Vlo each 64x72 bf16 (pad 8) = 9216B -> 36864B; x2.
// Q staged once (aliased into stage 0 area), then lives in registers.
// ---------------------------------------------------------------------------
#define ASTG 36864
#define ATTN_SMEM (2 * ASTG)
__global__ void __launch_bounds__(256, 1)
attn_kernel(const __nv_bfloat16* __restrict__ Qh_, const __nv_bfloat16* __restrict__ Ql_,
            const __nv_bfloat16* __restrict__ Kh_, const __nv_bfloat16* __restrict__ Kl_,
            const __nv_bfloat16* __restrict__ Vh_, const __nv_bfloat16* __restrict__ Vl_,
            __nv_bfloat16* __restrict__ Ch, __nv_bfloat16* __restrict__ Cl)
{
    extern __shared__ __align__(16) unsigned char dsm[];
    const unsigned smb = sptr(dsm);
    const int tid = threadIdx.x, w = tid >> 5, lane = tid & 31;
    const int q0 = blockIdx.x * 128;
    const int h = blockIdx.y, b = blockIdx.z;
    const long base = (long)((b << 3) + h) * (2048 * 64);

    // ---- Q tile -> smem (aliased in stage0) -> registers ----
#pragma unroll
    for (int c = 0; c < 8; c++) {
        int idx = tid + c * 256;                 // 0..2047
        int p = idx >> 10, r = (idx >> 3) & 127, q = idx & 7;
        const __nv_bfloat16* src = (p ? Ql_ : Qh_) + base + (long)(q0 + r) * 64 + q * 8;
        cpasync16(smb + p * 18432 + r * 144 + q * 16, src);
    }
    cpcommit(); cpwait<0>();
    __syncthreads();

    unsigned qh[4][4], ql[4][4];
#pragma unroll
    for (int ks = 0; ks < 4; ks++) {
        unsigned off = (w * 16 + (lane & 15)) * 144 + (ks * 16 + ((lane >> 4) << 3)) * 2;
        ldsm4(qh[ks], smb + off);
        ldsm4(ql[ks], smb + 18432 + off);
    }
    __syncthreads();

    float o[8][4];
#pragma unroll
    for (int j = 0; j < 8; j++)
#pragma unroll
        for (int i = 0; i < 4; i++) o[j][i] = 0.f;
    float rm[2] = {-1e30f, -1e30f}, rl[2] = {0.f, 0.f};

#pragma unroll 1
    for (int t = -1; t < 32; t++) {
        int lt = t + 1;
        if (lt < 32) {  // prefetch tile lt
            unsigned sdst = smb + (lt & 1) * ASTG;
            long coff = base + (long)lt * 64 * 64;
#pragma unroll
            for (int c = 0; c < 8; c++) {
                int idx = tid + c * 256;
                int p = idx >> 9, r = (idx >> 3) & 63, q = idx & 7;
                const __nv_bfloat16* sp = (p == 0) ? Kh_ : (p == 1) ? Kl_
                                         : (p == 2) ? Vh_ : Vl_;
                cpasync16(sdst + p * 9216 + r * 144 + q * 16, sp + coff + r * 64 + q * 8);
            }
            cpcommit();
        }
        if (t < 0) continue;
        if (t < 31) cpwait<1>(); else cpwait<0>();
        __syncthreads();

        unsigned stb = smb + (t & 1) * ASTG;

        // ---- S = Q @ K^T ----
        float s[8][4];
#pragma unroll
        for (int j = 0; j < 8; j++)
#pragma unroll
            for (int i = 0; i < 4; i++) s[j][i] = 0.f;

#pragma unroll
        for (int ks = 0; ks < 4; ks++) {
#pragma unroll
            for (int np = 0; np < 4; np++) {
                unsigned boff = ((np * 16 + (lane & 7) + ((lane >> 4) << 3)) * 144
                                 + (ks * 16 + ((lane >> 3) & 1) * 8) * 2);
                unsigned bh[4], bl[4];
                ldsm4(bh, stb + boff);
                ldsm4(bl, stb + 9216 + boff);
                mma16816(s[np * 2],     qh[ks], bh);
                mma16816(s[np * 2],     qh[ks], bl);
                mma16816(s[np * 2],     ql[ks], bh);
                mma16816(s[np * 2 + 1], qh[ks], bh + 2);
                mma16816(s[np * 2 + 1], qh[ks], bl + 2);
                mma16816(s[np * 2 + 1], ql[ks], bh + 2);
            }
        }

        // ---- online softmax ----
#pragma unroll
        for (int rr = 0; rr < 2; rr++) {
            float mt = -1e30f;
#pragma unroll
            for (int j = 0; j < 8; j++)
                mt = fmaxf(mt, fmaxf(s[j][rr * 2], s[j][rr * 2 + 1]));
            mt = fmaxf(mt, __shfl_xor_sync(0xffffffffu, mt, 1));
            mt = fmaxf(mt, __shfl_xor_sync(0xffffffffu, mt, 2));
            float mn = fmaxf(rm[rr], mt);
            float corr = __expf(rm[rr] - mn);
            rm[rr] = mn;
            float ls = 0.f;
#pragma unroll
            for (int j = 0; j < 8; j++) {
                float p0 = __expf(s[j][rr * 2] - mn);
                float p1 = __expf(s[j][rr * 2 + 1] - mn);
                s[j][rr * 2] = p0; s[j][rr * 2 + 1] = p1;
                ls += p0 + p1;
            }
            ls += __shfl_xor_sync(0xffffffffu, ls, 1);
            ls += __shfl_xor_sync(0xffffffffu, ls, 2);
            rl[rr] = rl[rr] * corr + ls;
#pragma unroll
            for (int j = 0; j < 8; j++) {
                o[j][rr * 2] *= corr; o[j][rr * 2 + 1] *= corr;
            }
        }

        // ---- P fragments (S C-frag layout == PV A-frag layout) ----
        unsigned ph[4][4], pl[4][4];
#pragma unroll
        for (int kc = 0; kc < 4; kc++) {
            split2(s[2 * kc][0],     s[2 * kc][1],     ph[kc][0], pl[kc][0]);
            split2(s[2 * kc][2],     s[2 * kc][3],     ph[kc][1], pl[kc][1]);
            split2(s[2 * kc + 1][0], s[2 * kc + 1][1], ph[kc][2], pl[kc][2]);
            split2(s[2 * kc + 1][2], s[2 * kc + 1][3], ph[kc][3], pl[kc][3]);
        }

        // ---- O += P @ V ----
#pragma unroll
        for (int ks = 0; ks < 4; ks++) {
            unsigned vrow = ks * 16 + (lane & 7) + ((lane >> 3) & 1) * 8;
#pragma unroll
            for (int dp = 0; dp < 4; dp++) {
                unsigned off = vrow * 144 + (dp * 16 + ((lane >> 4) << 3)) * 2;
                unsigned bh[4], bl[4];
                ldsm4t(bh, stb + 18432 + off);
                ldsm4t(bl, stb + 27648 + off);
                mma16816(o[dp * 2],     ph[ks], bh);
                mma16816(o[dp * 2],     ph[ks], bl);
                mma16816(o[dp * 2],     pl[ks], bh);
                mma16816(o[dp * 2 + 1], ph[ks], bh + 2);
                mma16816(o[dp * 2 + 1], ph[ks], bl + 2);
                mma16816(o[dp * 2 + 1], pl[ks], bh + 2);
            }
        }
        __syncthreads();
    }

    // ---- normalize, split, write ctx planes [B,S,D] ----
#pragma unroll
    for (int rr = 0; rr < 2; rr++) {
        float inv = 1.f / rl[rr];
        int rg = q0 + w * 16 + (lane >> 2) + rr * 8;
#pragma unroll
        for (int j = 0; j < 8; j++) {
            int col = h * 64 + j * 8 + (lane & 3) * 2;
            int oix = (b * 2048 + rg) * 512 + col;
            unsigned hv, lv;
            split2(o[j][rr * 2] * inv, o[j][rr * 2 + 1] * inv, hv, lv);
            *(unsigned*)&Ch[oix] = hv;
            *(unsigned*)&Cl[oix] = lv;
        }
    }
}

// ---------------------------------------------------------------------------
extern "C" void kernel_launch(void* const* d_in, const int* in_sizes, int n_in,
                              void* d_out, int out_size)
{
    const float* q  = (const float*)d_in[0];
    const float* k  = (const float*)d_in[1];
    const float* v  = (const float*)d_in[2];
    const float* Wq = (const float*)d_in[3];
    const float* bq = (const float*)d_in[4];
    const float* Wk = (const float*)d_in[5];
    const float* bk = (const float*)d_in[6];
    const float* Wv = (const float*)d_in[7];
    const float* bv = (const float*)d_in[8];
    const float* Wo = (const float*)d_in[9];
    const float* bo = (const float*)d_in[10];

    __nv_bfloat16 *qh, *ql, *kh, *kl, *vh, *vl;
    __nv_bfloat16 *wqh, *wql, *wkh, *wkl, *wvh, *wvl, *woh, *wol;
    __nv_bfloat16 *Qh, *Ql, *Kh, *Kl, *Vh, *Vl, *ch, *cl;
    cudaGetSymbolAddress((void**)&qh, g_qh);   cudaGetSymbolAddress((void**)&ql, g_ql);
    cudaGetSymbolAddress((void**)&kh, g_kh);   cudaGetSymbolAddress((void**)&kl, g_kl);
    cudaGetSymbolAddress((void**)&vh, g_vh);   cudaGetSymbolAddress((void**)&vl, g_vl);
    cudaGetSymbolAddress((void**)&wqh, g_wqh); cudaGetSymbolAddress((void**)&wql, g_wql);
    cudaGetSymbolAddress((void**)&wkh, g_wkh); cudaGetSymbolAddress((void**)&wkl, g_wkl);
    cudaGetSymbolAddress((void**)&wvh, g_wvh); cudaGetSymbolAddress((void**)&wvl, g_wvl);
    cudaGetSymbolAddress((void**)&woh, g_woh); cudaGetSymbolAddress((void**)&wol, g_wol);
    cudaGetSymbolAddress((void**)&Qh, g_Qh);   cudaGetSymbolAddress((void**)&Ql, g_Ql);
    cudaGetSymbolAddress((void**)&Kh, g_Kh);   cudaGetSymbolAddress((void**)&Kl, g_Kl);
    cudaGetSymbolAddress((void**)&Vh, g_Vh);   cudaGetSymbolAddress((void**)&Vl, g_Vl);
    cudaGetSymbolAddress((void**)&ch, g_ch);   cudaGetSymbolAddress((void**)&cl, g_cl);

    cudaFuncSetAttribute(gemm_bf16<0>, cudaFuncAttributeMaxDynamicSharedMemorySize, 2 * GSTG);
    cudaFuncSetAttribute(gemm_bf16<1>, cudaFuncAttributeMaxDynamicSharedMemorySize, 2 * GSTG);
    cudaFuncSetAttribute(attn_kernel, cudaFuncAttributeMaxDynamicSharedMemorySize, ATTN_SMEM);

    // 0) convert inputs + weights to split planes
    convert_kernel<<<2048, 256>>>(q, qh, ql, MD / 4);
    convert_kernel<<<2048, 256>>>(k, kh, kl, MD / 4);
    convert_kernel<<<2048, 256>>>(v, vh, vl, MD / 4);
    convert_kernel<<<256, 256>>>(Wq, wqh, wql, WD / 4);
    convert_kernel<<<256, 256>>>(Wk, wkh, wkl, WD / 4);
    convert_kernel<<<256, 256>>>(Wv, wvh, wvl, WD / 4);
    convert_kernel<<<256, 256>>>(Wo, woh, wol, WD / 4);

    // 1) projections (Q pre-scaled by 1/sqrt(HD)=0.125)
    dim3 gg(4, 64);
    gemm_bf16<1><<<gg, 256, 2 * GSTG>>>(qh, ql, wqh, wql, bq, 0.125f, nullptr, Qh, Ql);
    gemm_bf16<1><<<gg, 256, 2 * GSTG>>>(kh, kl, wkh, wkl, bk, 1.0f,   nullptr, Kh, Kl);
    gemm_bf16<1><<<gg, 256, 2 * GSTG>>>(vh, vl, wvh, wvl, bv, 1.0f,   nullptr, Vh, Vl);

    // 2) attention
    attn_kernel<<<dim3(16, 8, 4), 256, ATTN_SMEM>>>(Qh, Ql, Kh, Kl, Vh, Vl, ch, cl);

    // 3) output projection
    gemm_bf16<0><<<gg, 256, 2 * GSTG>>>(ch, cl, woh, wol, bo, 1.0f, (float*)d_out, nullptr, nullptr);
}

// round 4
// speedup vs baseline: 2.9035x; 1.1427x over previous
#include <cuda_runtime.h>
#include <cuda_bf16.h>

// ---------------------------------------------------------------------------
// MHA, bf16 split-precision (hi+lo) tensor cores, cp.async pipelines.
// B=4, S=2048, D=512, H=8, HD=64.
//  0) one convert kernel: q,k,v,W* fp32 -> bf16 hi/lo planes
//  1) proj GEMMs (split-plane out, [B,H,S,HD] remap, Q scaled by 0.125*log2e)
//  2) flash attn: 128-thr CTAs, 64 q-rows, 3 CTA/SM, log2-domain softmax
//  3) out GEMM (split-plane in, fp32 out + bias)
// ---------------------------------------------------------------------------

#define DI __device__ __forceinline__

DI unsigned sptr(const void* p) { return (unsigned)__cvta_generic_to_shared(p); }

DI void cpasync16(unsigned dst, const void* src) {
    asm volatile("cp.async.cg.shared.global [%0], [%1], 16;" :: "r"(dst), "l"(src));
}
DI void cpcommit() { asm volatile("cp.async.commit_group;"); }
template <int N> DI void cpwait() { asm volatile("cp.async.wait_group %0;" :: "n"(N)); }

DI void ldsm4(unsigned* r, unsigned a) {
    asm volatile("ldmatrix.sync.aligned.m8n8.x4.shared.b16 {%0,%1,%2,%3}, [%4];"
                 : "=r"(r[0]), "=r"(r[1]), "=r"(r[2]), "=r"(r[3]) : "r"(a));
}
DI void ldsm4t(unsigned* r, unsigned a) {
    asm volatile("ldmatrix.sync.aligned.m8n8.x4.trans.shared.b16 {%0,%1,%2,%3}, [%4];"
                 : "=r"(r[0]), "=r"(r[1]), "=r"(r[2]), "=r"(r[3]) : "r"(a));
}
DI void mma16816(float* c, const unsigned* a, const unsigned* b) {
    asm volatile(
        "mma.sync.aligned.m16n8k16.row.col.f32.bf16.bf16.f32 "
        "{%0,%1,%2,%3},{%4,%5,%6,%7},{%8,%9},{%0,%1,%2,%3};"
        : "+f"(c[0]), "+f"(c[1]), "+f"(c[2]), "+f"(c[3])
        : "r"(a[0]), "r"(a[1]), "r"(a[2]), "r"(a[3]), "r"(b[0]), "r"(b[1]));
}
DI unsigned pkbf(float e0, float e1) {   // pack (e0,e1) -> bf16x2, e0 low
    unsigned r;
    asm("cvt.rn.bf16x2.f32 %0, %1, %2;" : "=r"(r) : "f"(e1), "f"(e0));
    return r;
}
DI float bfr(float x) { return __bfloat162float(__float2bfloat16(x)); }
DI void split2(float a, float b, unsigned& hi, unsigned& lo) {
    float ah = bfr(a), bh = bfr(b);
    hi = pkbf(ah, bh);
    lo = pkbf(a - ah, b - bh);
}
DI float ex2(float x) {  // 2^x via MUFU
    float r; asm("ex2.approx.f32 %0, %1;" : "=f"(r) : "f"(x)); return r;
}

// ---------------- scratch (allocation-free: device globals) ----------------
#define MD (8192 * 512)
#define WD (512 * 512)
__device__ __nv_bfloat16 g_qh[MD], g_ql[MD], g_kh[MD], g_kl[MD], g_vh[MD], g_vl[MD];
__device__ __nv_bfloat16 g_wqh[WD], g_wql[WD], g_wkh[WD], g_wkl[WD];
__device__ __nv_bfloat16 g_wvh[WD], g_wvl[WD], g_woh[WD], g_wol[WD];
__device__ __nv_bfloat16 g_Qh[MD], g_Ql[MD], g_Kh[MD], g_Kl[MD], g_Vh[MD], g_Vl[MD];
__device__ __nv_bfloat16 g_ch[MD], g_cl[MD];

// ---------------------------------------------------------------------------
// Single convert kernel for all 7 tensors (3 of MD, 4 of WD), float4 granular.
// ---------------------------------------------------------------------------
struct CvtArgs {
    const float* src[7];
    __nv_bfloat16* hi[7];
    __nv_bfloat16* lo[7];
};
#define MD4 (MD / 4)
#define WD4 (WD / 4)
__global__ void convert_all(CvtArgs a)
{
    const int total = 3 * MD4 + 4 * WD4;
    for (int i = blockIdx.x * blockDim.x + threadIdx.x; i < total;
         i += gridDim.x * blockDim.x) {
        int s, off;
        if (i < 3 * MD4) { s = i >> 20; off = i & (MD4 - 1); }
        else { int j = i - 3 * MD4; s = 3 + (j >> 16); off = j & (WD4 - 1); }
        float4 v = ((const float4*)a.src[s])[off];
        float hx = bfr(v.x), hy = bfr(v.y), hz = bfr(v.z), hw = bfr(v.w);
        uint2 h, l;
        h.x = pkbf(hx, hy);             h.y = pkbf(hz, hw);
        l.x = pkbf(v.x - hx, v.y - hy); l.y = pkbf(v.z - hz, v.w - hw);
        ((uint2*)a.hi[s])[off] = h;
        ((uint2*)a.lo[s])[off] = l;
    }
}

// ---------------------------------------------------------------------------
// GEMM: C[8192,512] = A @ W^T (+bias) (*scale). bf16 hi/lo planes in.
// Tile 128Mx128N, BK=32, 256 thr, warps 2(M)x4(N). 2-stage cp.async.
// ---------------------------------------------------------------------------
#define GSTG 40960
template <int OUT_SPLIT>
__global__ void __launch_bounds__(256, 2)
gemm_bf16(const __nv_bfloat16* __restrict__ Ahi, const __nv_bfloat16* __restrict__ Alo,
          const __nv_bfloat16* __restrict__ Whi, const __nv_bfloat16* __restrict__ Wlo,
          const float* __restrict__ bias, float scale,
          float* __restrict__ Cf,
          __nv_bfloat16* __restrict__ Chi, __nv_bfloat16* __restrict__ Clo)
{
    extern __shared__ __align__(16) unsigned char dsm[];
    const unsigned smb = sptr(dsm);
    const int tid = threadIdx.x, w = tid >> 5, lane = tid & 31;
    const int wm = w >> 2, wn = w & 3;
    const int m0 = blockIdx.y * 128, n0 = blockIdx.x * 128;

    float acc[4][4][4];
#pragma unroll
    for (int a = 0; a < 4; a++)
#pragma unroll
        for (int b = 0; b < 4; b++)
#pragma unroll
            for (int c = 0; c < 4; c++) acc[a][b][c] = 0.f;

#pragma unroll 1
    for (int step = -1; step < 16; step++) {
        int lt = step + 1;
        if (lt < 16) {
            unsigned sdst = smb + (lt & 1) * GSTG;
            int k0 = lt * 32;
#pragma unroll
            for (int c = 0; c < 8; c++) {
                int idx = tid + c * 256;
                int p = idx >> 9, r = (idx >> 2) & 127, q = idx & 3;
                const __nv_bfloat16* sp = (p == 0) ? Ahi : (p == 1) ? Alo
                                         : (p == 2) ? Whi : Wlo;
                int grow = ((p < 2) ? m0 : n0) + r;
                cpasync16(sdst + p * 10240 + r * 80 + q * 16,
                          sp + grow * 512 + k0 + q * 8);
            }
            cpcommit();
        }
        if (step < 0) continue;
        if (step < 15) cpwait<1>(); else cpwait<0>();
        __syncthreads();

        unsigned sa = smb + (step & 1) * GSTG;
#pragma unroll
        for (int ks = 0; ks < 2; ks++) {
            unsigned bh[2][4], bl[2][4];
#pragma unroll
            for (int np = 0; np < 2; np++) {
                unsigned boff = ((wn * 32 + np * 16 + (lane & 7) + ((lane >> 4) << 3)) * 40
                                 + ks * 16 + ((lane >> 3) & 1) * 8) * 2;
                ldsm4(bh[np], sa + 20480 + boff);
                ldsm4(bl[np], sa + 30720 + boff);
            }
#pragma unroll
            for (int mi = 0; mi < 4; mi++) {
                unsigned aoff = ((wm * 64 + mi * 16 + (lane & 15)) * 40
                                 + ks * 16 + ((lane >> 4) << 3)) * 2;
                unsigned ah[4], al[4];
                ldsm4(ah, sa + aoff);
                ldsm4(al, sa + 10240 + aoff);
#pragma unroll
                for (int np = 0; np < 2; np++) {
                    mma16816(acc[mi][np * 2],     ah, bh[np]);
                    mma16816(acc[mi][np * 2],     ah, bl[np]);
                    mma16816(acc[mi][np * 2],     al, bh[np]);
                    mma16816(acc[mi][np * 2 + 1], ah, bh[np] + 2);
                    mma16816(acc[mi][np * 2 + 1], ah, bl[np] + 2);
                    mma16816(acc[mi][np * 2 + 1], al, bh[np] + 2);
                }
            }
        }
        __syncthreads();
    }

    // epilogue
#pragma unroll
    for (int mi = 0; mi < 4; mi++) {
#pragma unroll
        for (int j = 0; j < 4; j++) {
            int n = n0 + wn * 32 + (j >> 1) * 16 + (j & 1) * 8 + (lane & 3) * 2;
            float b0 = bias[n], b1 = bias[n + 1];
#pragma unroll
            for (int rr = 0; rr < 2; rr++) {
                int m = m0 + wm * 64 + mi * 16 + (lane >> 2) + rr * 8;
                float v0 = (acc[mi][j][rr * 2]     + b0) * scale;
                float v1 = (acc[mi][j][rr * 2 + 1] + b1) * scale;
                if (OUT_SPLIT) {
                    int bb = m >> 11, s = m & 2047, hh = n >> 6, hd = n & 63;
                    int o = (((bb << 3) + hh) * 2048 + s) * 64 + hd;
                    unsigned hv, lv; split2(v0, v1, hv, lv);
                    *(unsigned*)&Chi[o] = hv;
                    *(unsigned*)&Clo[o] = lv;
                } else {
                    *(float2*)&Cf[m * 512 + n] = make_float2(v0, v1);
                }
            }
        }
    }
}

// ---------------------------------------------------------------------------
// Flash attention. Block = (b,h,64 q rows), 128 threads (4 warps x 16 rows).
// 3 CTAs/SM (smem 72KB, regs ~141) -> cross-CTA softmax/MMA overlap.
// Softmax in log2 domain (Q pre-scaled by 0.125*log2e; ex2.approx).
// smem/stage: Khi,Klo,Vhi,Vlo each 64x72 bf16 = 9216B -> 36864B; 2 stages.
// ---------------------------------------------------------------------------
#define ASTG 36864
#define ATTN_SMEM (2 * ASTG)
__global__ void __launch_bounds__(128, 3)
attn_kernel(const __nv_bfloat16* __restrict__ Qh_, const __nv_bfloat16* __restrict__ Ql_,
            const __nv_bfloat16* __restrict__ Kh_, const __nv_bfloat16* __restrict__ Kl_,
            const __nv_bfloat16* __restrict__ Vh_, const __nv_bfloat16* __restrict__ Vl_,
            __nv_bfloat16* __restrict__ Ch, __nv_bfloat16* __restrict__ Cl)
{
    extern __shared__ __align__(16) unsigned char dsm[];
    const unsigned smb = sptr(dsm);
    const int tid = threadIdx.x, w = tid >> 5, lane = tid & 31;
    const int q0 = blockIdx.x * 64;
    const int h = blockIdx.y, b = blockIdx.z;
    const long base = (long)((b << 3) + h) * (2048 * 64);

    // ---- Q tile (64 rows) -> smem (aliased in stage0) -> registers ----
#pragma unroll
    for (int c = 0; c < 8; c++) {
        int idx = tid + c * 128;                 // 0..1023
        int p = idx >> 9, r = (idx >> 3) & 63, q = idx & 7;
        const __nv_bfloat16* src = (p ? Ql_ : Qh_) + base + (long)(q0 + r) * 64 + q * 8;
        cpasync16(smb + p * 9216 + r * 144 + q * 16, src);
    }
    cpcommit(); cpwait<0>();
    __syncthreads();

    unsigned qh[4][4], ql[4][4];
#pragma unroll
    for (int ks = 0; ks < 4; ks++) {
        unsigned off = (w * 16 + (lane & 15)) * 144 + (ks * 16 + ((lane >> 4) << 3)) * 2;
        ldsm4(qh[ks], smb + off);
        ldsm4(ql[ks], smb + 9216 + off);
    }
    __syncthreads();

    float o[8][4];
#pragma unroll
    for (int j = 0; j < 8; j++)
#pragma unroll
        for (int i = 0; i < 4; i++) o[j][i] = 0.f;
    float rm[2] = {-1e30f, -1e30f}, rl[2] = {0.f, 0.f};

#pragma unroll 1
    for (int t = -1; t < 32; t++) {
        int lt = t + 1;
        if (lt < 32) {  // prefetch tile lt
            unsigned sdst = smb + (lt & 1) * ASTG;
            long coff = base + (long)lt * 64 * 64;
#pragma unroll
            for (int c = 0; c < 16; c++) {
                int idx = tid + c * 128;         // 0..2047
                int p = idx >> 9, r = (idx >> 3) & 63, q = idx & 7;
                const __nv_bfloat16* sp = (p == 0) ? Kh_ : (p == 1) ? Kl_
                                         : (p == 2) ? Vh_ : Vl_;
                cpasync16(sdst + p * 9216 + r * 144 + q * 16, sp + coff + r * 64 + q * 8);
            }
            cpcommit();
        }
        if (t < 0) continue;
        if (t < 31) cpwait<1>(); else cpwait<0>();
        __syncthreads();

        unsigned stb = smb + (t & 1) * ASTG;

        // ---- S = Q @ K^T (log2-domain scores) ----
        float s[8][4];
#pragma unroll
        for (int j = 0; j < 8; j++)
#pragma unroll
            for (int i = 0; i < 4; i++) s[j][i] = 0.f;

#pragma unroll
        for (int ks = 0; ks < 4; ks++) {
#pragma unroll
            for (int np = 0; np < 4; np++) {
                unsigned boff = ((np * 16 + (lane & 7) + ((lane >> 4) << 3)) * 144
                                 + (ks * 16 + ((lane >> 3) & 1) * 8) * 2);
                unsigned bh[4], bl[4];
                ldsm4(bh, stb + boff);
                ldsm4(bl, stb + 9216 + boff);
                mma16816(s[np * 2],     qh[ks], bh);
                mma16816(s[np * 2],     qh[ks], bl);
                mma16816(s[np * 2],     ql[ks], bh);
                mma16816(s[np * 2 + 1], qh[ks], bh + 2);
                mma16816(s[np * 2 + 1], qh[ks], bl + 2);
                mma16816(s[np * 2 + 1], ql[ks], bh + 2);
            }
        }

        // ---- online softmax (base-2) ----
#pragma unroll
        for (int rr = 0; rr < 2; rr++) {
            float mt = -1e30f;
#pragma unroll
            for (int j = 0; j < 8; j++)
                mt = fmaxf(mt, fmaxf(s[j][rr * 2], s[j][rr * 2 + 1]));
            mt = fmaxf(mt, __shfl_xor_sync(0xffffffffu, mt, 1));
            mt = fmaxf(mt, __shfl_xor_sync(0xffffffffu, mt, 2));
            float mn = fmaxf(rm[rr], mt);
            float corr = ex2(rm[rr] - mn);
            rm[rr] = mn;
            float ls = 0.f;
#pragma unroll
            for (int j = 0; j < 8; j++) {
                float p0 = ex2(s[j][rr * 2] - mn);
                float p1 = ex2(s[j][rr * 2 + 1] - mn);
                s[j][rr * 2] = p0; s[j][rr * 2 + 1] = p1;
                ls += p0 + p1;
            }
            ls += __shfl_xor_sync(0xffffffffu, ls, 1);
            ls += __shfl_xor_sync(0xffffffffu, ls, 2);
            rl[rr] = rl[rr] * corr + ls;
#pragma unroll
            for (int j = 0; j < 8; j++) {
                o[j][rr * 2] *= corr; o[j][rr * 2 + 1] *= corr;
            }
        }

        // ---- P fragments (S C-frag layout == PV A-frag layout) ----
        unsigned ph[4][4], pl[4][4];
#pragma unroll
        for (int kc = 0; kc < 4; kc++) {
            split2(s[2 * kc][0],     s[2 * kc][1],     ph[kc][0], pl[kc][0]);
            split2(s[2 * kc][2],     s[2 * kc][3],     ph[kc][1], pl[kc][1]);
            split2(s[2 * kc + 1][0], s[2 * kc + 1][1], ph[kc][2], pl[kc][2]);
            split2(s[2 * kc + 1][2], s[2 * kc + 1][3], ph[kc][3], pl[kc][3]);
        }

        // ---- O += P @ V ----
#pragma unroll
        for (int ks = 0; ks < 4; ks++) {
            unsigned vrow = ks * 16 + (lane & 7) + ((lane >> 3) & 1) * 8;
#pragma unroll
            for (int dp = 0; dp < 4; dp++) {
                unsigned off = vrow * 144 + (dp * 16 + ((lane >> 4) << 3)) * 2;
                unsigned bh[4], bl[4];
                ldsm4t(bh, stb + 18432 + off);
                ldsm4t(bl, stb + 27648 + off);
                mma16816(o[dp * 2],     ph[ks], bh);
                mma16816(o[dp * 2],     ph[ks], bl);
                mma16816(o[dp * 2],     pl[ks], bh);
                mma16816(o[dp * 2 + 1], ph[ks], bh + 2);
                mma16816(o[dp * 2 + 1], ph[ks], bl + 2);
                mma16816(o[dp * 2 + 1], pl[ks], bh + 2);
            }
        }
        __syncthreads();
    }

    // ---- normalize, split, write ctx planes [B,S,D] ----
#pragma unroll
    for (int rr = 0; rr < 2; rr++) {
        float inv = 1.f / rl[rr];
        int rg = q0 + w * 16 + (lane >> 2) + rr * 8;
#pragma unroll
        for (int j = 0; j < 8; j++) {
            int col = h * 64 + j * 8 + (lane & 3) * 2;
            int oix = (b * 2048 + rg) * 512 + col;
            unsigned hv, lv;
            split2(o[j][rr * 2] * inv, o[j][rr * 2 + 1] * inv, hv, lv);
            *(unsigned*)&Ch[oix] = hv;
            *(unsigned*)&Cl[oix] = lv;
        }
    }
}

// ---------------------------------------------------------------------------
extern "C" void kernel_launch(void* const* d_in, const int* in_sizes, int n_in,
                              void* d_out, int out_size)
{
    const float* q  = (const float*)d_in[0];
    const float* k  = (const float*)d_in[1];
    const float* v  = (const float*)d_in[2];
    const float* Wq = (const float*)d_in[3];
    const float* bq = (const float*)d_in[4];
    const float* Wk = (const float*)d_in[5];
    const float* bk = (const float*)d_in[6];
    const float* Wv = (const float*)d_in[7];
    const float* bv = (const float*)d_in[8];
    const float* Wo = (const float*)d_in[9];
    const float* bo = (const float*)d_in[10];

    __nv_bfloat16 *qh, *ql, *kh, *kl, *vh, *vl;
    __nv_bfloat16 *wqh, *wql, *wkh, *wkl, *wvh, *wvl, *woh, *wol;
    __nv_bfloat16 *Qh, *Ql, *Kh, *Kl, *Vh, *Vl, *ch, *cl;
    cudaGetSymbolAddress((void**)&qh, g_qh);   cudaGetSymbolAddress((void**)&ql, g_ql);
    cudaGetSymbolAddress((void**)&kh, g_kh);   cudaGetSymbolAddress((void**)&kl, g_kl);
    cudaGetSymbolAddress((void**)&vh, g_vh);   cudaGetSymbolAddress((void**)&vl, g_vl);
    cudaGetSymbolAddress((void**)&wqh, g_wqh); cudaGetSymbolAddress((void**)&wql, g_wql);
    cudaGetSymbolAddress((void**)&wkh, g_wkh); cudaGetSymbolAddress((void**)&wkl, g_wkl);
    cudaGetSymbolAddress((void**)&wvh, g_wvh); cudaGetSymbolAddress((void**)&wvl, g_wvl);
    cudaGetSymbolAddress((void**)&woh, g_woh); cudaGetSymbolAddress((void**)&wol, g_wol);
    cudaGetSymbolAddress((void**)&Qh, g_Qh);   cudaGetSymbolAddress((void**)&Ql, g_Ql);
    cudaGetSymbolAddress((void**)&Kh, g_Kh);   cudaGetSymbolAddress((void**)&Kl, g_Kl);
    cudaGetSymbolAddress((void**)&Vh, g_Vh);   cudaGetSymbolAddress((void**)&Vl, g_Vl);
    cudaGetSymbolAddress((void**)&ch, g_ch);   cudaGetSymbolAddress((void**)&cl, g_cl);

    cudaFuncSetAttribute(gemm_bf16<0>, cudaFuncAttributeMaxDynamicSharedMemorySize, 2 * GSTG);
    cudaFuncSetAttribute(gemm_bf16<1>, cudaFuncAttributeMaxDynamicSharedMemorySize, 2 * GSTG);
    cudaFuncSetAttribute(attn_kernel, cudaFuncAttributeMaxDynamicSharedMemorySize, ATTN_SMEM);

    // 0) one convert kernel for everything
    CvtArgs ca;
    ca.src[0] = q;  ca.hi[0] = qh;  ca.lo[0] = ql;
    ca.src[1] = k;  ca.hi[1] = kh;  ca.lo[1] = kl;
    ca.src[2] = v;  ca.hi[2] = vh;  ca.lo[2] = vl;
    ca.src[3] = Wq; ca.hi[3] = wqh; ca.lo[3] = wql;
    ca.src[4] = Wk; ca.hi[4] = wkh; ca.lo[4] = wkl;
    ca.src[5] = Wv; ca.hi[5] = wvh; ca.lo[5] = wvl;
    ca.src[6] = Wo; ca.hi[6] = woh; ca.lo[6] = wol;
    convert_all<<<2048, 256>>>(ca);

    // 1) projections (Q pre-scaled by 0.125*log2e for base-2 softmax)
    dim3 gg(4, 64);
    const float qscale = 0.125f * 1.44269504088896f;
    gemm_bf16<1><<<gg, 256, 2 * GSTG>>>(qh, ql, wqh, wql, bq, qscale, nullptr, Qh, Ql);
    gemm_bf16<1><<<gg, 256, 2 * GSTG>>>(kh, kl, wkh, wkl, bk, 1.0f,   nullptr, Kh, Kl);
    gemm_bf16<1><<<gg, 256, 2 * GSTG>>>(vh, vl, wvh, wvl, bv, 1.0f,   nullptr, Vh, Vl);

    // 2) attention: 1024 CTAs x 128 threads, 64 q-rows each
    attn_kernel<<<dim3(32, 8, 4), 128, ATTN_SMEM>>>(Qh, Ql, Kh, Kl, Vh, Vl, ch, cl);

    // 3) output projection
    gemm_bf16<0><<<gg, 256, 2 * GSTG>>>(ch, cl, woh, wol, bo, 1.0f, (float*)d_out, nullptr, nullptr);
}